// round 11
// baseline (speedup 1.0000x reference)
#include <cuda_runtime.h>
#include <cuda_bf16.h>
#include <cstdint>

// ---------------------------------------------------------------------------
// Problem constants
// ---------------------------------------------------------------------------
#define BB    4
#define HH    64
#define WW    64
#define CC    768
#define WS    14
#define NH    12
#define HD    64
#define NWIN  5                 // windows per side (70/14)
#define BW    (BB*NWIN*NWIN)    // 100 windows
#define TT    (WS*WS)           // 196 tokens per window
#define M1    (BW*TT)           // 19600 window-token rows
#define NT    (BB*HH*WW)        // 16384 image tokens
#define BH    (BW*NH)           // 1200 attention batches

// ---------------------------------------------------------------------------
// Device scratch (static __device__ arrays: allocation-free, graph-safe)
// ---------------------------------------------------------------------------
__device__ __nv_bfloat16 g_win_h [(size_t)M1 * CC];
__device__ __nv_bfloat16 g_win_l [(size_t)M1 * CC];
__device__ float g_q     [(size_t)BH * TT * HD];
__device__ float g_kt    [(size_t)BH * HD * TT];
__device__ float g_v     [(size_t)BH * TT * HD];
__device__ float g_relh  [(size_t)BH * TT * WS];
__device__ float g_relw  [(size_t)BH * TT * WS];
__device__ float g_attn  [(size_t)BH * TT * TT];
__device__ __nv_bfloat16 g_ao_h [(size_t)M1 * CC];
__device__ __nv_bfloat16 g_ao_l [(size_t)M1 * CC];
__device__ float g_x2    [(size_t)NT * CC];
__device__ __nv_bfloat16 g_ln2_h[(size_t)NT * CC];
__device__ __nv_bfloat16 g_ln2_l[(size_t)NT * CC];
__device__ __nv_bfloat16 g_mid_h[(size_t)NT * 4 * CC];
__device__ __nv_bfloat16 g_mid_l[(size_t)NT * 4 * CC];
// split weights
__device__ __nv_bfloat16 g_wqkv_h[(size_t)CC * 3 * CC];
__device__ __nv_bfloat16 g_wqkv_l[(size_t)CC * 3 * CC];
__device__ __nv_bfloat16 g_wp_h  [(size_t)CC * CC];
__device__ __nv_bfloat16 g_wp_l  [(size_t)CC * CC];
__device__ __nv_bfloat16 g_w1_h  [(size_t)CC * 4 * CC];
__device__ __nv_bfloat16 g_w1_l  [(size_t)CC * 4 * CC];
__device__ __nv_bfloat16 g_w2_h  [(size_t)4 * CC * CC];
__device__ __nv_bfloat16 g_w2_l  [(size_t)4 * CC * CC];

// ---------------------------------------------------------------------------
// Helpers
// ---------------------------------------------------------------------------
__device__ __forceinline__ void split2(float v, __nv_bfloat16& h, __nv_bfloat16& l) {
    h = __float2bfloat16(v);
    l = __float2bfloat16(v - __bfloat162float(h));
}

__device__ __forceinline__ float2 block_reduce_sum2(float a, float b) {
    #pragma unroll
    for (int o = 16; o; o >>= 1) {
        a += __shfl_xor_sync(0xffffffffu, a, o);
        b += __shfl_xor_sync(0xffffffffu, b, o);
    }
    __shared__ float sa[8], sb[8];
    int w = threadIdx.x >> 5, l = threadIdx.x & 31;
    if (l == 0) { sa[w] = a; sb[w] = b; }
    __syncthreads();
    if (w == 0) {
        a = (l < 8) ? sa[l] : 0.0f;
        b = (l < 8) ? sb[l] : 0.0f;
        #pragma unroll
        for (int o = 4; o; o >>= 1) {
            a += __shfl_xor_sync(0xffffffffu, a, o);
            b += __shfl_xor_sync(0xffffffffu, b, o);
        }
        if (l == 0) { sa[0] = a; sb[0] = b; }
    }
    __syncthreads();
    return make_float2(sa[0], sb[0]);
}

// cp.async 16B (zero-fill when pred false)
__device__ __forceinline__ void cp16(__nv_bfloat16* dst, const __nv_bfloat16* src, bool pred) {
    uint32_t d = (uint32_t)__cvta_generic_to_shared(dst);
    int sz = pred ? 16 : 0;
    asm volatile("cp.async.cg.shared.global [%0], [%1], 16, %2;\n"
                 :: "r"(d), "l"(src), "r"(sz));
}
__device__ __forceinline__ void cp_commit() {
    asm volatile("cp.async.commit_group;\n");
}
template <int N>
__device__ __forceinline__ void cp_wait() {
    asm volatile("cp.async.wait_group %0;\n" :: "n"(N));
}

// ---------------------------------------------------------------------------
// K0: split fp32 -> bf16 hi/lo (for weights)
// ---------------------------------------------------------------------------
__global__ void __launch_bounds__(256)
split_kernel(const float* __restrict__ src,
             __nv_bfloat16* __restrict__ hi, __nv_bfloat16* __restrict__ lo, int n4) {
    int i = blockIdx.x * 256 + threadIdx.x;
    if (i >= n4) return;
    float4 v = reinterpret_cast<const float4*>(src)[i];
    __nv_bfloat16 h0,l0,h1,l1,h2,l2,h3,l3;
    split2(v.x,h0,l0); split2(v.y,h1,l1); split2(v.z,h2,l2); split2(v.w,h3,l3);
    __nv_bfloat162* H = reinterpret_cast<__nv_bfloat162*>(hi);
    __nv_bfloat162* L = reinterpret_cast<__nv_bfloat162*>(lo);
    H[2*i]   = __nv_bfloat162(h0, h1);
    H[2*i+1] = __nv_bfloat162(h2, h3);
    L[2*i]   = __nv_bfloat162(l0, l1);
    L[2*i+1] = __nv_bfloat162(l2, l3);
}

// ---------------------------------------------------------------------------
// K1: LayerNorm1 + window partition (zero pad) -> bf16 hi/lo
// ---------------------------------------------------------------------------
__global__ void __launch_bounds__(256)
ln1_partition_kernel(const float* __restrict__ x,
                     const float* __restrict__ gamma,
                     const float* __restrict__ beta,
                     __nv_bfloat16* __restrict__ wh,
                     __nv_bfloat16* __restrict__ wl) {
    int wrow = blockIdx.x;
    int bw = wrow / TT, t = wrow % TT;
    int b  = bw / (NWIN*NWIN);
    int wr = bw % (NWIN*NWIN);
    int wi = wr / NWIN, wj = wr % NWIN;
    int i  = t / WS, j = t % WS;
    int gh = wi*WS + i, gw = wj*WS + j;

    size_t base = (size_t)wrow * CC;
    int tid = threadIdx.x;
    if (gh >= HH || gw >= WW) {
        __nv_bfloat16 z = __float2bfloat16(0.0f);
        wh[base+tid] = z; wh[base+tid+256] = z; wh[base+tid+512] = z;
        wl[base+tid] = z; wl[base+tid+256] = z; wl[base+tid+512] = z;
        return;
    }
    const float* xr = x + (size_t)(((b*HH + gh)*WW) + gw) * CC;
    float v0 = xr[tid], v1 = xr[tid+256], v2 = xr[tid+512];
    float2 r = block_reduce_sum2(v0+v1+v2, v0*v0 + v1*v1 + v2*v2);
    float mean = r.x * (1.0f/CC);
    float var  = r.y * (1.0f/CC) - mean*mean;
    float inv  = rsqrtf(var + 1e-6f);
    float o0 = (v0-mean)*inv*gamma[tid]     + beta[tid];
    float o1 = (v1-mean)*inv*gamma[tid+256] + beta[tid+256];
    float o2 = (v2-mean)*inv*gamma[tid+512] + beta[tid+512];
    __nv_bfloat16 h, l;
    split2(o0,h,l); wh[base+tid]     = h; wl[base+tid]     = l;
    split2(o1,h,l); wh[base+tid+256] = h; wl[base+tid+256] = l;
    split2(o2,h,l); wh[base+tid+512] = h; wl[base+tid+512] = l;
}

// ---------------------------------------------------------------------------
// K2: LayerNorm2 -> bf16 hi/lo
// ---------------------------------------------------------------------------
__global__ void __launch_bounds__(256)
ln2_kernel(const float* __restrict__ in,
           const float* __restrict__ gamma,
           const float* __restrict__ beta,
           __nv_bfloat16* __restrict__ oh, __nv_bfloat16* __restrict__ ol) {
    size_t row = blockIdx.x;
    const float* xr = in + row * CC;
    size_t base = row * CC;
    int tid = threadIdx.x;
    float v0 = xr[tid], v1 = xr[tid+256], v2 = xr[tid+512];
    float2 r = block_reduce_sum2(v0+v1+v2, v0*v0 + v1*v1 + v2*v2);
    float mean = r.x * (1.0f/CC);
    float var  = r.y * (1.0f/CC) - mean*mean;
    float inv  = rsqrtf(var + 1e-6f);
    float o0 = (v0-mean)*inv*gamma[tid]     + beta[tid];
    float o1 = (v1-mean)*inv*gamma[tid+256] + beta[tid+256];
    float o2 = (v2-mean)*inv*gamma[tid+512] + beta[tid+512];
    __nv_bfloat16 h, l;
    split2(o0,h,l); oh[base+tid]     = h; ol[base+tid]     = l;
    split2(o1,h,l); oh[base+tid+256] = h; ol[base+tid+256] = l;
    split2(o2,h,l); oh[base+tid+512] = h; ol[base+tid+512] = l;
}

// ---------------------------------------------------------------------------
// Tensor-core GEMM (bf16x3 split precision), 2-stage cp.async pipeline.
//   C = A @ B with fused epilogues selected by `mode`:
//     0: Cf fp32 (+bias, +residual, optional gelu)
//     1: split bf16 hi/lo out (+bias, optional gelu)         [fc1]
//     2: qkv scatter -> q[b][t][d], kt[b][d][t], v[b][t][d]  [qkv]
//     3: window-reverse + residual(x image layout) -> Cf=x2  [proj]
// Tile 128x128x32, 256 threads = 8 warps 4(M)x2(N), warp tile 32x64.
// Requires N % 128 == 0, K % 32 == 0.
// ---------------------------------------------------------------------------
__device__ __forceinline__ void ldsm_x4(uint32_t* r, uint32_t a) {
    asm volatile("ldmatrix.sync.aligned.m8n8.x4.shared.b16 {%0,%1,%2,%3}, [%4];"
        : "=r"(r[0]), "=r"(r[1]), "=r"(r[2]), "=r"(r[3]) : "r"(a));
}
__device__ __forceinline__ void ldsm_x2t(uint32_t* r, uint32_t a) {
    asm volatile("ldmatrix.sync.aligned.m8n8.x2.trans.shared.b16 {%0,%1}, [%2];"
        : "=r"(r[0]), "=r"(r[1]) : "r"(a));
}
__device__ __forceinline__ void mma16816(float* c, const uint32_t* a, const uint32_t* b) {
    asm volatile(
        "mma.sync.aligned.m16n8k16.row.col.f32.bf16.bf16.f32 "
        "{%0,%1,%2,%3}, {%4,%5,%6,%7}, {%8,%9}, {%0,%1,%2,%3};"
        : "+f"(c[0]), "+f"(c[1]), "+f"(c[2]), "+f"(c[3])
        : "r"(a[0]), "r"(a[1]), "r"(a[2]), "r"(a[3]), "r"(b[0]), "r"(b[1]));
}

#define MT_AS 40    // 32 + 8 pad (elems)
#define MT_BS 136   // 128 + 8 pad (elems)
#define A_STAGE_E (2*128*MT_AS)
#define B_STAGE_E (2*32*MT_BS)
#define STAGE_E   (A_STAGE_E + B_STAGE_E)
#define MMA_SMEM_BYTES (2 * STAGE_E * 2)

#define AS_(st,h,r,c) ds[(size_t)(st)*STAGE_E + (h)*(128*MT_AS) + (r)*MT_AS + (c)]
#define BS_(st,h,r,c) ds[(size_t)(st)*STAGE_E + A_STAGE_E + (h)*(32*MT_BS) + (r)*MT_BS + (c)]

#define LOAD_STAGE(st, k0)                                                     \
  {                                                                            \
    _Pragma("unroll")                                                          \
    for (int h = 0; h < 2; h++) {                                              \
      const __nv_bfloat16* pa = Asrc[h] + (size_t)gA * lda + (k0) + acol;      \
      cp16(&AS_((st),h,arow,acol),   pa,     okA);                             \
      cp16(&AS_((st),h,arow,acol+8), pa + 8, okA);                             \
      const __nv_bfloat16* pb = Bsrc[h] + (size_t)((k0)+brow) * ldb + n0 + bcol; \
      cp16(&BS_((st),h,brow,bcol),   pb,     true);                            \
      cp16(&BS_((st),h,brow,bcol+8), pb + 8, true);                            \
    }                                                                          \
    cp_commit();                                                               \
  }

__global__ void __launch_bounds__(256)
mma_gemm_kernel(const __nv_bfloat16* __restrict__ Ah, const __nv_bfloat16* __restrict__ Al,
                const __nv_bfloat16* __restrict__ Bh, const __nv_bfloat16* __restrict__ Bl,
                int M, int N, int K, int lda, int ldb, int ldc,
                const float* __restrict__ bias,
                const float* __restrict__ residual,
                float* __restrict__ Cf,
                __nv_bfloat16* __restrict__ Chi, __nv_bfloat16* __restrict__ Clo,
                float* __restrict__ q_out, float* __restrict__ kt_out,
                float* __restrict__ v_out,
                int mode, int gelu_flag) {
    extern __shared__ __align__(16) __nv_bfloat16 ds[];

    int tid  = threadIdx.x;
    int wid  = tid >> 5, lane = tid & 31;
    int wm   = wid >> 1, wn = wid & 1;
    int m0   = blockIdx.y * 128;
    int n0   = blockIdx.x * 128;

    float acc[2][8][4];
    #pragma unroll
    for (int mt = 0; mt < 2; mt++)
        #pragma unroll
        for (int nt = 0; nt < 8; nt++)
            #pragma unroll
            for (int c = 0; c < 4; c++) acc[mt][nt][c] = 0.0f;

    // gmem->smem mapping: each thread moves 16 contiguous bf16 (2x16B) per matrix
    int arow = tid >> 1,  acol = (tid & 1) * 16;   // A: 128 rows x 32 cols
    int brow = tid >> 3,  bcol = (tid & 7) * 16;   // B: 32 rows x 128 cols

    const __nv_bfloat16* Asrc[2] = {Ah, Al};
    const __nv_bfloat16* Bsrc[2] = {Bh, Bl};

    int gmA = m0 + arow;
    bool okA = gmA < M;
    int gA = okA ? gmA : 0;

    int a_r = (lane & 15), a_c = (lane >> 4) * 8;
    int b_r = (lane & 15), b_c = wn * 64;

    const int KT = K >> 5;
    LOAD_STAGE(0, 0);

    for (int ktile = 0; ktile < KT; ktile++) {
        int cur = ktile & 1;
        if (ktile + 1 < KT) {
            LOAD_STAGE(cur ^ 1, (ktile + 1) << 5);
            cp_wait<1>();
        } else {
            cp_wait<0>();
        }
        __syncthreads();

        #pragma unroll
        for (int ks = 0; ks < 2; ks++) {
            uint32_t afr[2][2][4];   // [hi/lo][mtile][4]
            #pragma unroll
            for (int h = 0; h < 2; h++)
                #pragma unroll
                for (int mt = 0; mt < 2; mt++) {
                    uint32_t addr = (uint32_t)__cvta_generic_to_shared(
                        &AS_(cur, h, wm*32 + mt*16 + a_r, ks*16 + a_c));
                    ldsm_x4(afr[h][mt], addr);
                }
            #pragma unroll
            for (int nt = 0; nt < 8; nt++) {
                uint32_t bfr[2][2];
                #pragma unroll
                for (int h = 0; h < 2; h++) {
                    uint32_t addr = (uint32_t)__cvta_generic_to_shared(
                        &BS_(cur, h, ks*16 + b_r, b_c + nt*8));
                    ldsm_x2t(bfr[h], addr);
                }
                #pragma unroll
                for (int mt = 0; mt < 2; mt++) {
                    mma16816(acc[mt][nt], afr[0][mt], bfr[0]);   // hi*hi
                    mma16816(acc[mt][nt], afr[0][mt], bfr[1]);   // hi*lo
                    mma16816(acc[mt][nt], afr[1][mt], bfr[0]);   // lo*hi
                }
            }
        }
        __syncthreads();
    }

    // epilogue
    int gid = lane >> 2, tig = lane & 3;
    #pragma unroll
    for (int mt = 0; mt < 2; mt++) {
        #pragma unroll
        for (int half = 0; half < 2; half++) {
            int gm = m0 + wm*32 + mt*16 + gid + half*8;
            if (gm >= M) continue;

            int bwq = 0, tq = 0;
            long long ntrow = -1;
            if (mode == 2) { bwq = gm / TT; tq = gm % TT; }
            else if (mode == 3) {
                int bw = gm / TT, t = gm % TT;
                int b = bw / (NWIN*NWIN), wr = bw % (NWIN*NWIN);
                int gh = (wr/NWIN)*WS + t/WS;
                int gw = (wr%NWIN)*WS + t%WS;
                if (gh >= HH || gw >= WW) continue;   // padded window row: unused
                ntrow = (long long)(b*HH + gh)*WW + gw;
            }

            #pragma unroll
            for (int nt = 0; nt < 8; nt++) {
                int col = n0 + wn*64 + nt*8 + tig*2;
                float v0 = acc[mt][nt][half*2 + 0];
                float v1 = acc[mt][nt][half*2 + 1];
                if (bias) { v0 += bias[col]; v1 += bias[col+1]; }
                if (gelu_flag) {
                    v0 = 0.5f * v0 * (1.0f + erff(v0 * 0.70710678118654752440f));
                    v1 = 0.5f * v1 * (1.0f + erff(v1 * 0.70710678118654752440f));
                }
                if (mode == 0) {
                    if (residual) {
                        float2 rr = *reinterpret_cast<const float2*>(
                            residual + (size_t)gm * ldc + col);
                        v0 += rr.x; v1 += rr.y;
                    }
                    *reinterpret_cast<float2*>(Cf + (size_t)gm * ldc + col) =
                        make_float2(v0, v1);
                } else if (mode == 1) {
                    __nv_bfloat16 h0,l0,h1,l1;
                    split2(v0,h0,l0); split2(v1,h1,l1);
                    *reinterpret_cast<__nv_bfloat162*>(Chi + (size_t)gm * ldc + col) =
                        __nv_bfloat162(h0, h1);
                    *reinterpret_cast<__nv_bfloat162*>(Clo + (size_t)gm * ldc + col) =
                        __nv_bfloat162(l0, l1);
                } else if (mode == 2) {
                    int s = col / CC;
                    int r = col - s*CC;
                    int h = r >> 6, d = r & 63;
                    int bb = bwq*NH + h;
                    if (s == 0) {
                        *reinterpret_cast<float2*>(
                            q_out + ((size_t)bb*TT + tq)*HD + d) = make_float2(v0, v1);
                    } else if (s == 1) {
                        size_t kb = (size_t)bb * HD * TT;
                        kt_out[kb + (size_t)d*TT + tq]     = v0;
                        kt_out[kb + (size_t)(d+1)*TT + tq] = v1;
                    } else {
                        *reinterpret_cast<float2*>(
                            v_out + ((size_t)bb*TT + tq)*HD + d) = make_float2(v0, v1);
                    }
                } else { // mode 3: window reverse + residual(x)
                    float2 rr = *reinterpret_cast<const float2*>(
                        residual + ntrow * CC + col);
                    *reinterpret_cast<float2*>(Cf + ntrow * CC + col) =
                        make_float2(v0 + rr.x, v1 + rr.y);
                }
            }
        }
    }
}

// ---------------------------------------------------------------------------
// fp32 SGEMM (attention path): C[bz] = alpha*A@B + relpos bias, OR
// PV mode (oh != null): merged-head split-bf16 output.
// ---------------------------------------------------------------------------
#define GBM 128
#define GBN 64
#define GBK 16

__global__ void __launch_bounds__(256)
gemm_kernel(const float* __restrict__ A, const float* __restrict__ B,
            float* __restrict__ C,
            int M, int N, int K, int lda, int ldb, int ldc,
            long long sA, long long sB, long long sC,
            const float* __restrict__ relh,
            const float* __restrict__ relw,
            float alpha,
            __nv_bfloat16* __restrict__ oh, __nv_bfloat16* __restrict__ ol) {
    __shared__ float As[GBK][GBM + 4];
    __shared__ float Bs[GBK][GBN];

    int bz = blockIdx.z;
    const float* Ab = A + (long long)bz * sA;
    const float* Bb = B + (long long)bz * sB;

    int m0 = blockIdx.y * GBM;
    int n0 = blockIdx.x * GBN;
    int tid = threadIdx.x;
    int tx = tid & 15;
    int ty = tid >> 4;

    float acc[8][4];
    #pragma unroll
    for (int i = 0; i < 8; i++)
        #pragma unroll
        for (int j = 0; j < 4; j++) acc[i][j] = 0.0f;

    int ar  = tid >> 2;
    int ac4 = (tid & 3) * 4;
    int bkr = tid >> 4;
    int bnc = (tid & 15) * 4;

    for (int k0 = 0; k0 < K; k0 += GBK) {
        #pragma unroll
        for (int half = 0; half < 2; half++) {
            int r  = ar + half * 64;
            int gm = m0 + r;
            float4 av = make_float4(0.f, 0.f, 0.f, 0.f);
            if (gm < M && (k0 + ac4) < K)
                av = *reinterpret_cast<const float4*>(Ab + (long long)gm * lda + k0 + ac4);
            As[ac4+0][r] = av.x;
            As[ac4+1][r] = av.y;
            As[ac4+2][r] = av.z;
            As[ac4+3][r] = av.w;
        }
        {
            float4 bv = make_float4(0.f, 0.f, 0.f, 0.f);
            if ((k0 + bkr) < K && (n0 + bnc) < N)
                bv = *reinterpret_cast<const float4*>(Bb + (long long)(k0 + bkr) * ldb + n0 + bnc);
            *reinterpret_cast<float4*>(&Bs[bkr][bnc]) = bv;
        }
        __syncthreads();

        #pragma unroll
        for (int kk = 0; kk < GBK; kk++) {
            float4 a0 = *reinterpret_cast<const float4*>(&As[kk][ty*8]);
            float4 a1 = *reinterpret_cast<const float4*>(&As[kk][ty*8 + 4]);
            float4 b0 = *reinterpret_cast<const float4*>(&Bs[kk][tx*4]);
            float a[8] = {a0.x, a0.y, a0.z, a0.w, a1.x, a1.y, a1.z, a1.w};
            float bb[4] = {b0.x, b0.y, b0.z, b0.w};
            #pragma unroll
            for (int i = 0; i < 8; i++)
                #pragma unroll
                for (int j = 0; j < 4; j++)
                    acc[i][j] = fmaf(a[i], bb[j], acc[i][j]);
        }
        __syncthreads();
    }

    int bwp = bz / NH, hp = bz % NH;
    #pragma unroll
    for (int i = 0; i < 8; i++) {
        int gm = m0 + ty*8 + i;
        if (gm >= M) continue;
        #pragma unroll
        for (int j = 0; j < 4; j++) {
            int gn = n0 + tx*4 + j;
            if (gn >= N) continue;
            float v = alpha * acc[i][j];
            if (relh) {
                long long rb = (long long)bz * (TT*WS) + (long long)gm * WS;
                v += relh[rb + gn / WS] + relw[rb + gn % WS];
            }
            if (C) {
                C[(long long)bz * sC + (long long)gm * ldc + gn] = v;
            } else {
                __nv_bfloat16 hh, ll;
                split2(v, hh, ll);
                size_t idx = ((size_t)bwp*TT + gm)*CC + hp*HD + gn;
                oh[idx] = hh;
                ol[idx] = ll;
            }
        }
    }
}

// ---------------------------------------------------------------------------
// K4: decomposed relative position bias (padded smem: conflict-free)
// ---------------------------------------------------------------------------
__global__ void __launch_bounds__(256)
relbias_kernel(const float* __restrict__ q,
               const float* __restrict__ rph,
               const float* __restrict__ rpw,
               float* __restrict__ relh, float* __restrict__ relw) {
    int ih = blockIdx.x;        // 0..13
    int b  = blockIdx.y;        // 0..BH-1
    __shared__ float qs[WS][HD+1];
    __shared__ float hs[2*WS-1][HD+1];
    __shared__ float ws[2*WS-1][HD+1];
    int tid = threadIdx.x;
    for (int idx = tid; idx < WS*HD; idx += 256) {
        int iw = idx / HD, d = idx % HD;
        qs[iw][d] = q[((size_t)b * TT + ih*WS + iw) * HD + d];
    }
    for (int idx = tid; idx < (2*WS-1)*HD; idx += 256) {
        int r = idx / HD, d = idx % HD;
        hs[r][d] = rph[idx];
        ws[r][d] = rpw[idx];
    }
    __syncthreads();
    for (int tt = tid; tt < 2*TT; tt += 256) {
        int which = tt / TT;
        int l = tt % TT;
        int iw = l / WS, kx = l % WS;
        float sum = 0.0f;
        if (which == 0) {
            int rr = ih - kx + (WS - 1);
            #pragma unroll
            for (int d = 0; d < HD; d++) sum = fmaf(qs[iw][d], hs[rr][d], sum);
            relh[(size_t)b * (TT*WS) + (size_t)(ih*WS + iw) * WS + kx] = sum;
        } else {
            int rr = iw - kx + (WS - 1);
            #pragma unroll
            for (int d = 0; d < HD; d++) sum = fmaf(qs[iw][d], ws[rr][d], sum);
            relw[(size_t)b * (TT*WS) + (size_t)(ih*WS + iw) * WS + kx] = sum;
        }
    }
}

// ---------------------------------------------------------------------------
// K5: softmax over rows of length 196
// ---------------------------------------------------------------------------
__global__ void __launch_bounds__(256)
softmax_kernel(float* __restrict__ attn) {
    int warp = threadIdx.x >> 5, lane = threadIdx.x & 31;
    long long row = (long long)blockIdx.x * 8 + warp;
    if (row >= (long long)BH * TT) return;
    float* p = attn + row * TT;
    float v[7];
    float mx = -1e30f;
    #pragma unroll
    for (int i = 0; i < 7; i++) {
        int idx = lane + i*32;
        v[i] = (idx < TT) ? p[idx] : -1e30f;
        mx = fmaxf(mx, v[i]);
    }
    #pragma unroll
    for (int o = 16; o; o >>= 1) mx = fmaxf(mx, __shfl_xor_sync(0xffffffffu, mx, o));
    float s = 0.0f;
    #pragma unroll
    for (int i = 0; i < 7; i++) {
        v[i] = expf(v[i] - mx);
        s += v[i];
    }
    #pragma unroll
    for (int o = 16; o; o >>= 1) s += __shfl_xor_sync(0xffffffffu, s, o);
    float inv = 1.0f / s;
    #pragma unroll
    for (int i = 0; i < 7; i++) {
        int idx = lane + i*32;
        if (idx < TT) p[idx] = v[i] * inv;
    }
}

// ---------------------------------------------------------------------------
// Host launcher
// ---------------------------------------------------------------------------
static void launch_mma(const __nv_bfloat16* Ah, const __nv_bfloat16* Al,
                       const __nv_bfloat16* Bh, const __nv_bfloat16* Bl,
                       int M, int N, int K, int lda, int ldb, int ldc,
                       const float* bias, const float* res,
                       float* Cf, __nv_bfloat16* Chi, __nv_bfloat16* Clo,
                       float* qo, float* kto, float* vo,
                       int mode, int gelu) {
    dim3 grid(N / 128, (M + 127) / 128);
    mma_gemm_kernel<<<grid, 256, MMA_SMEM_BYTES>>>(
        Ah, Al, Bh, Bl, M, N, K, lda, ldb, ldc,
        bias, res, Cf, Chi, Clo, qo, kto, vo, mode, gelu);
}

extern "C" void kernel_launch(void* const* d_in, const int* in_sizes, int n_in,
                              void* d_out, int out_size) {
    const float* x      = (const float*)d_in[0];
    const float* ln1_g  = (const float*)d_in[1];
    const float* ln1_b  = (const float*)d_in[2];
    const float* w_qkv  = (const float*)d_in[3];
    const float* b_qkv  = (const float*)d_in[4];
    const float* w_proj = (const float*)d_in[5];
    const float* b_proj = (const float*)d_in[6];
    const float* rph    = (const float*)d_in[7];
    const float* rpw    = (const float*)d_in[8];
    const float* ln2_g  = (const float*)d_in[9];
    const float* ln2_b  = (const float*)d_in[10];
    const float* w_fc1  = (const float*)d_in[11];
    const float* b_fc1  = (const float*)d_in[12];
    const float* w_fc2  = (const float*)d_in[13];
    const float* b_fc2  = (const float*)d_in[14];
    float* out = (float*)d_out;

    cudaFuncSetAttribute(mma_gemm_kernel,
                         cudaFuncAttributeMaxDynamicSharedMemorySize, MMA_SMEM_BYTES);

    float *p_q, *p_kt, *p_v, *p_relh, *p_relw, *p_attn, *p_x2;
    __nv_bfloat16 *p_win_h, *p_win_l, *p_ao_h, *p_ao_l, *p_ln2_h, *p_ln2_l,
                  *p_mid_h, *p_mid_l,
                  *p_wqkv_h, *p_wqkv_l, *p_wp_h, *p_wp_l,
                  *p_w1_h, *p_w1_l, *p_w2_h, *p_w2_l;
    cudaGetSymbolAddress((void**)&p_q,     g_q);
    cudaGetSymbolAddress((void**)&p_kt,    g_kt);
    cudaGetSymbolAddress((void**)&p_v,     g_v);
    cudaGetSymbolAddress((void**)&p_relh,  g_relh);
    cudaGetSymbolAddress((void**)&p_relw,  g_relw);
    cudaGetSymbolAddress((void**)&p_attn,  g_attn);
    cudaGetSymbolAddress((void**)&p_x2,    g_x2);
    cudaGetSymbolAddress((void**)&p_win_h, g_win_h);
    cudaGetSymbolAddress((void**)&p_win_l, g_win_l);
    cudaGetSymbolAddress((void**)&p_ao_h,  g_ao_h);
    cudaGetSymbolAddress((void**)&p_ao_l,  g_ao_l);
    cudaGetSymbolAddress((void**)&p_ln2_h, g_ln2_h);
    cudaGetSymbolAddress((void**)&p_ln2_l, g_ln2_l);
    cudaGetSymbolAddress((void**)&p_mid_h, g_mid_h);
    cudaGetSymbolAddress((void**)&p_mid_l, g_mid_l);
    cudaGetSymbolAddress((void**)&p_wqkv_h, g_wqkv_h);
    cudaGetSymbolAddress((void**)&p_wqkv_l, g_wqkv_l);
    cudaGetSymbolAddress((void**)&p_wp_h,   g_wp_h);
    cudaGetSymbolAddress((void**)&p_wp_l,   g_wp_l);
    cudaGetSymbolAddress((void**)&p_w1_h,   g_w1_h);
    cudaGetSymbolAddress((void**)&p_w1_l,   g_w1_l);
    cudaGetSymbolAddress((void**)&p_w2_h,   g_w2_h);
    cudaGetSymbolAddress((void**)&p_w2_l,   g_w2_l);

    // 0. split weights to bf16 hi/lo
    {
        int n;
        n = CC*3*CC/4;  split_kernel<<<(n+255)/256, 256>>>(w_qkv,  p_wqkv_h, p_wqkv_l, n);
        n = CC*CC/4;    split_kernel<<<(n+255)/256, 256>>>(w_proj, p_wp_h,   p_wp_l,   n);
        n = CC*4*CC/4;  split_kernel<<<(n+255)/256, 256>>>(w_fc1,  p_w1_h,   p_w1_l,   n);
        n = 4*CC*CC/4;  split_kernel<<<(n+255)/256, 256>>>(w_fc2,  p_w2_h,   p_w2_l,   n);
    }

    // 1. LN1 + window partition (bf16 hi/lo)
    ln1_partition_kernel<<<M1, 256>>>(x, ln1_g, ln1_b, p_win_h, p_win_l);

    // 2. QKV projection (tensor cores) with fused repack -> q, k^T, v (fp32)
    launch_mma(p_win_h, p_win_l, p_wqkv_h, p_wqkv_l,
               M1, 3*CC, CC, CC, 3*CC, 3*CC,
               b_qkv, nullptr, nullptr, nullptr, nullptr,
               p_q, p_kt, p_v, /*mode=*/2, 0);

    // 3. Rel-pos bias terms
    {
        dim3 grid(WS, BH);
        relbias_kernel<<<grid, 256>>>(p_q, rph, rpw, p_relh, p_relw);
    }

    // 4. Scores: attn = 0.125 * q@k^T + relh + relw (fp32, batched 1200)
    {
        dim3 grid((TT + GBN - 1)/GBN, (TT + GBM - 1)/GBM, BH);
        gemm_kernel<<<grid, 256>>>(p_q, p_kt, p_attn, TT, TT, HD, HD, TT, TT,
                                   (long long)TT*HD, (long long)HD*TT, (long long)TT*TT,
                                   p_relh, p_relw, 0.125f, nullptr, nullptr);
    }

    // 5. Softmax
    softmax_kernel<<<(BH*TT)/8, 256>>>(p_attn);

    // 6. PV: o = attn @ v (fp32, batched) with fused head-merge + bf16 split
    {
        dim3 grid((HD + GBN - 1)/GBN, (TT + GBM - 1)/GBM, BH);
        gemm_kernel<<<grid, 256>>>(p_attn, p_v, nullptr, TT, HD, TT, TT, HD, HD,
                                   (long long)TT*TT, (long long)TT*HD, 0,
                                   nullptr, nullptr, 1.0f, p_ao_h, p_ao_l);
    }

    // 7. Output projection (tensor cores) with fused window-reverse + residual -> x2
    launch_mma(p_ao_h, p_ao_l, p_wp_h, p_wp_l,
               M1, CC, CC, CC, CC, CC,
               b_proj, x, p_x2, nullptr, nullptr,
               nullptr, nullptr, nullptr, /*mode=*/3, 0);

    // 8. LN2 -> bf16 hi/lo
    ln2_kernel<<<NT, 256>>>(p_x2, ln2_g, ln2_b, p_ln2_h, p_ln2_l);

    // 9. fc1 + GELU (tensor cores) -> bf16 hi/lo intermediate
    launch_mma(p_ln2_h, p_ln2_l, p_w1_h, p_w1_l,
               NT, 4*CC, CC, CC, 4*CC, 4*CC,
               b_fc1, nullptr, nullptr, p_mid_h, p_mid_l,
               nullptr, nullptr, nullptr, /*mode=*/1, 1);

    // 10. fc2 + bias + residual(x2) (tensor cores) -> d_out fp32
    launch_mma(p_mid_h, p_mid_l, p_w2_h, p_w2_l,
               NT, CC, 4*CC, 4*CC, CC, CC,
               b_fc2, p_x2, out, nullptr, nullptr,
               nullptr, nullptr, nullptr, /*mode=*/0, 0);
}

// round 12
// speedup vs baseline: 1.0583x; 1.0583x over previous
#include <cuda_runtime.h>
#include <cuda_bf16.h>
#include <cstdint>

// ---------------------------------------------------------------------------
// Problem constants
// ---------------------------------------------------------------------------
#define BB    4
#define HH    64
#define WW    64
#define CC    768
#define WS    14
#define NH    12
#define HD    64
#define NWIN  5                 // windows per side (70/14)
#define BW    (BB*NWIN*NWIN)    // 100 windows
#define TT    (WS*WS)           // 196 tokens per window
#define M1    (BW*TT)           // 19600 window-token rows
#define NT    (BB*HH*WW)        // 16384 image tokens
#define BH    (BW*NH)           // 1200 attention batches
#define KTP   224               // padded token stride (7*32, 16B-aligned bf16 rows)

// ---------------------------------------------------------------------------
// Device scratch (static __device__ arrays: allocation-free, graph-safe)
// ---------------------------------------------------------------------------
__device__ __nv_bfloat16 g_win_h [(size_t)M1 * CC];
__device__ __nv_bfloat16 g_win_l [(size_t)M1 * CC];
__device__ __nv_bfloat16 g_q_h  [(size_t)BH * TT * HD];
__device__ __nv_bfloat16 g_q_l  [(size_t)BH * TT * HD];
__device__ __nv_bfloat16 g_kt_h [(size_t)BH * HD * KTP];   // cols 196..223 stay 0
__device__ __nv_bfloat16 g_kt_l [(size_t)BH * HD * KTP];
__device__ __nv_bfloat16 g_v_h  [(size_t)BH * TT * HD];
__device__ __nv_bfloat16 g_v_l  [(size_t)BH * TT * HD];
__device__ float g_relh  [(size_t)BH * TT * WS];
__device__ float g_relw  [(size_t)BH * TT * WS];
__device__ float g_attn  [(size_t)BH * TT * TT];
__device__ __nv_bfloat16 g_at_h [(size_t)BH * TT * KTP];   // softmax out, split
__device__ __nv_bfloat16 g_at_l [(size_t)BH * TT * KTP];
__device__ __nv_bfloat16 g_ao_h [(size_t)M1 * CC];
__device__ __nv_bfloat16 g_ao_l [(size_t)M1 * CC];
__device__ float g_x2    [(size_t)NT * CC];
__device__ __nv_bfloat16 g_ln2_h[(size_t)NT * CC];
__device__ __nv_bfloat16 g_ln2_l[(size_t)NT * CC];
__device__ __nv_bfloat16 g_mid_h[(size_t)NT * 4 * CC];
__device__ __nv_bfloat16 g_mid_l[(size_t)NT * 4 * CC];
// split weights
__device__ __nv_bfloat16 g_wqkv_h[(size_t)CC * 3 * CC];
__device__ __nv_bfloat16 g_wqkv_l[(size_t)CC * 3 * CC];
__device__ __nv_bfloat16 g_wp_h  [(size_t)CC * CC];
__device__ __nv_bfloat16 g_wp_l  [(size_t)CC * CC];
__device__ __nv_bfloat16 g_w1_h  [(size_t)CC * 4 * CC];
__device__ __nv_bfloat16 g_w1_l  [(size_t)CC * 4 * CC];
__device__ __nv_bfloat16 g_w2_h  [(size_t)4 * CC * CC];
__device__ __nv_bfloat16 g_w2_l  [(size_t)4 * CC * CC];

// ---------------------------------------------------------------------------
// Helpers
// ---------------------------------------------------------------------------
__device__ __forceinline__ void split2(float v, __nv_bfloat16& h, __nv_bfloat16& l) {
    h = __float2bfloat16(v);
    l = __float2bfloat16(v - __bfloat162float(h));
}

__device__ __forceinline__ float2 block_reduce_sum2(float a, float b) {
    #pragma unroll
    for (int o = 16; o; o >>= 1) {
        a += __shfl_xor_sync(0xffffffffu, a, o);
        b += __shfl_xor_sync(0xffffffffu, b, o);
    }
    __shared__ float sa[8], sb[8];
    int w = threadIdx.x >> 5, l = threadIdx.x & 31;
    if (l == 0) { sa[w] = a; sb[w] = b; }
    __syncthreads();
    if (w == 0) {
        a = (l < 8) ? sa[l] : 0.0f;
        b = (l < 8) ? sb[l] : 0.0f;
        #pragma unroll
        for (int o = 4; o; o >>= 1) {
            a += __shfl_xor_sync(0xffffffffu, a, o);
            b += __shfl_xor_sync(0xffffffffu, b, o);
        }
        if (l == 0) { sa[0] = a; sb[0] = b; }
    }
    __syncthreads();
    return make_float2(sa[0], sb[0]);
}

// cp.async 16B (zero-fill when pred false)
__device__ __forceinline__ void cp16(__nv_bfloat16* dst, const __nv_bfloat16* src, bool pred) {
    uint32_t d = (uint32_t)__cvta_generic_to_shared(dst);
    int sz = pred ? 16 : 0;
    asm volatile("cp.async.cg.shared.global [%0], [%1], 16, %2;\n"
                 :: "r"(d), "l"(src), "r"(sz));
}
__device__ __forceinline__ void cp_commit() {
    asm volatile("cp.async.commit_group;\n");
}
template <int N>
__device__ __forceinline__ void cp_wait() {
    asm volatile("cp.async.wait_group %0;\n" :: "n"(N));
}

// ---------------------------------------------------------------------------
// K0: split fp32 -> bf16 hi/lo (for weights)
// ---------------------------------------------------------------------------
__global__ void __launch_bounds__(256)
split_kernel(const float* __restrict__ src,
             __nv_bfloat16* __restrict__ hi, __nv_bfloat16* __restrict__ lo, int n4) {
    int i = blockIdx.x * 256 + threadIdx.x;
    if (i >= n4) return;
    float4 v = reinterpret_cast<const float4*>(src)[i];
    __nv_bfloat16 h0,l0,h1,l1,h2,l2,h3,l3;
    split2(v.x,h0,l0); split2(v.y,h1,l1); split2(v.z,h2,l2); split2(v.w,h3,l3);
    __nv_bfloat162* H = reinterpret_cast<__nv_bfloat162*>(hi);
    __nv_bfloat162* L = reinterpret_cast<__nv_bfloat162*>(lo);
    H[2*i]   = __nv_bfloat162(h0, h1);
    H[2*i+1] = __nv_bfloat162(h2, h3);
    L[2*i]   = __nv_bfloat162(l0, l1);
    L[2*i+1] = __nv_bfloat162(l2, l3);
}

// ---------------------------------------------------------------------------
// K1: LayerNorm1 + window partition (zero pad) -> bf16 hi/lo
// ---------------------------------------------------------------------------
__global__ void __launch_bounds__(256)
ln1_partition_kernel(const float* __restrict__ x,
                     const float* __restrict__ gamma,
                     const float* __restrict__ beta,
                     __nv_bfloat16* __restrict__ wh,
                     __nv_bfloat16* __restrict__ wl) {
    int wrow = blockIdx.x;
    int bw = wrow / TT, t = wrow % TT;
    int b  = bw / (NWIN*NWIN);
    int wr = bw % (NWIN*NWIN);
    int wi = wr / NWIN, wj = wr % NWIN;
    int i  = t / WS, j = t % WS;
    int gh = wi*WS + i, gw = wj*WS + j;

    size_t base = (size_t)wrow * CC;
    int tid = threadIdx.x;
    if (gh >= HH || gw >= WW) {
        __nv_bfloat16 z = __float2bfloat16(0.0f);
        wh[base+tid] = z; wh[base+tid+256] = z; wh[base+tid+512] = z;
        wl[base+tid] = z; wl[base+tid+256] = z; wl[base+tid+512] = z;
        return;
    }
    const float* xr = x + (size_t)(((b*HH + gh)*WW) + gw) * CC;
    float v0 = xr[tid], v1 = xr[tid+256], v2 = xr[tid+512];
    float2 r = block_reduce_sum2(v0+v1+v2, v0*v0 + v1*v1 + v2*v2);
    float mean = r.x * (1.0f/CC);
    float var  = r.y * (1.0f/CC) - mean*mean;
    float inv  = rsqrtf(var + 1e-6f);
    float o0 = (v0-mean)*inv*gamma[tid]     + beta[tid];
    float o1 = (v1-mean)*inv*gamma[tid+256] + beta[tid+256];
    float o2 = (v2-mean)*inv*gamma[tid+512] + beta[tid+512];
    __nv_bfloat16 h, l;
    split2(o0,h,l); wh[base+tid]     = h; wl[base+tid]     = l;
    split2(o1,h,l); wh[base+tid+256] = h; wl[base+tid+256] = l;
    split2(o2,h,l); wh[base+tid+512] = h; wl[base+tid+512] = l;
}

// ---------------------------------------------------------------------------
// K2: LayerNorm2 -> bf16 hi/lo
// ---------------------------------------------------------------------------
__global__ void __launch_bounds__(256)
ln2_kernel(const float* __restrict__ in,
           const float* __restrict__ gamma,
           const float* __restrict__ beta,
           __nv_bfloat16* __restrict__ oh, __nv_bfloat16* __restrict__ ol) {
    size_t row = blockIdx.x;
    const float* xr = in + row * CC;
    size_t base = row * CC;
    int tid = threadIdx.x;
    float v0 = xr[tid], v1 = xr[tid+256], v2 = xr[tid+512];
    float2 r = block_reduce_sum2(v0+v1+v2, v0*v0 + v1*v1 + v2*v2);
    float mean = r.x * (1.0f/CC);
    float var  = r.y * (1.0f/CC) - mean*mean;
    float inv  = rsqrtf(var + 1e-6f);
    float o0 = (v0-mean)*inv*gamma[tid]     + beta[tid];
    float o1 = (v1-mean)*inv*gamma[tid+256] + beta[tid+256];
    float o2 = (v2-mean)*inv*gamma[tid+512] + beta[tid+512];
    __nv_bfloat16 h, l;
    split2(o0,h,l); oh[base+tid]     = h; ol[base+tid]     = l;
    split2(o1,h,l); oh[base+tid+256] = h; ol[base+tid+256] = l;
    split2(o2,h,l); oh[base+tid+512] = h; ol[base+tid+512] = l;
}

// ---------------------------------------------------------------------------
// MMA building blocks
// ---------------------------------------------------------------------------
__device__ __forceinline__ void ldsm_x4(uint32_t* r, uint32_t a) {
    asm volatile("ldmatrix.sync.aligned.m8n8.x4.shared.b16 {%0,%1,%2,%3}, [%4];"
        : "=r"(r[0]), "=r"(r[1]), "=r"(r[2]), "=r"(r[3]) : "r"(a));
}
__device__ __forceinline__ void ldsm_x2t(uint32_t* r, uint32_t a) {
    asm volatile("ldmatrix.sync.aligned.m8n8.x2.trans.shared.b16 {%0,%1}, [%2];"
        : "=r"(r[0]), "=r"(r[1]) : "r"(a));
}
__device__ __forceinline__ void mma16816(float* c, const uint32_t* a, const uint32_t* b) {
    asm volatile(
        "mma.sync.aligned.m16n8k16.row.col.f32.bf16.bf16.f32 "
        "{%0,%1,%2,%3}, {%4,%5,%6,%7}, {%8,%9}, {%0,%1,%2,%3};"
        : "+f"(c[0]), "+f"(c[1]), "+f"(c[2]), "+f"(c[3])
        : "r"(a[0]), "r"(a[1]), "r"(a[2]), "r"(a[3]), "r"(b[0]), "r"(b[1]));
}

#define MT_AS 40    // 32 + 8 pad (elems)
#define MT_BS 136   // 128 + 8 pad (elems)
#define A_STAGE_E (2*128*MT_AS)
#define B_STAGE_E (2*32*MT_BS)
#define STAGE_E   (A_STAGE_E + B_STAGE_E)
#define MMA_SMEM_BYTES (2 * STAGE_E * 2)

#define AS_(st,h,r,c) ds[(size_t)(st)*STAGE_E + (h)*(128*MT_AS) + (r)*MT_AS + (c)]
#define BS_(st,h,r,c) ds[(size_t)(st)*STAGE_E + A_STAGE_E + (h)*(32*MT_BS) + (r)*MT_BS + (c)]

// ---------------------------------------------------------------------------
// Tensor-core GEMM (bf16x3 split precision), 2-stage cp.async pipeline.
//   C = A @ B with fused epilogues selected by `mode`:
//     0: Cf fp32 (+bias, +residual, optional gelu)
//     1: split bf16 hi/lo out (+bias, optional gelu)              [fc1]
//     2: qkv scatter -> split bf16 q[b][t][d], kt[b][d][tpad], v  [qkv]
//     3: window-reverse + residual(x image layout) -> Cf=x2       [proj]
// ---------------------------------------------------------------------------
#define LOAD_STAGE(st, k0)                                                     \
  {                                                                            \
    _Pragma("unroll")                                                          \
    for (int h = 0; h < 2; h++) {                                              \
      const __nv_bfloat16* pa = Asrc[h] + (size_t)gA * lda + (k0) + acol;      \
      cp16(&AS_((st),h,arow,acol),   pa,     okA);                             \
      cp16(&AS_((st),h,arow,acol+8), pa + 8, okA);                             \
      const __nv_bfloat16* pb = Bsrc[h] + (size_t)((k0)+brow) * ldb + n0 + bcol; \
      cp16(&BS_((st),h,brow,bcol),   pb,     true);                            \
      cp16(&BS_((st),h,brow,bcol+8), pb + 8, true);                            \
    }                                                                          \
    cp_commit();                                                               \
  }

__global__ void __launch_bounds__(256)
mma_gemm_kernel(const __nv_bfloat16* __restrict__ Ah, const __nv_bfloat16* __restrict__ Al,
                const __nv_bfloat16* __restrict__ Bh, const __nv_bfloat16* __restrict__ Bl,
                int M, int N, int K, int lda, int ldb, int ldc,
                const float* __restrict__ bias,
                const float* __restrict__ residual,
                float* __restrict__ Cf,
                __nv_bfloat16* __restrict__ Chi, __nv_bfloat16* __restrict__ Clo,
                __nv_bfloat16* __restrict__ qh, __nv_bfloat16* __restrict__ ql,
                __nv_bfloat16* __restrict__ kth, __nv_bfloat16* __restrict__ ktl,
                __nv_bfloat16* __restrict__ vh, __nv_bfloat16* __restrict__ vl,
                int mode, int gelu_flag) {
    extern __shared__ __align__(16) __nv_bfloat16 ds[];

    int tid  = threadIdx.x;
    int wid  = tid >> 5, lane = tid & 31;
    int wm   = wid >> 1, wn = wid & 1;
    int m0   = blockIdx.y * 128;
    int n0   = blockIdx.x * 128;

    float acc[2][8][4];
    #pragma unroll
    for (int mt = 0; mt < 2; mt++)
        #pragma unroll
        for (int nt = 0; nt < 8; nt++)
            #pragma unroll
            for (int c = 0; c < 4; c++) acc[mt][nt][c] = 0.0f;

    int arow = tid >> 1,  acol = (tid & 1) * 16;   // A: 128 rows x 32 cols
    int brow = tid >> 3,  bcol = (tid & 7) * 16;   // B: 32 rows x 128 cols

    const __nv_bfloat16* Asrc[2] = {Ah, Al};
    const __nv_bfloat16* Bsrc[2] = {Bh, Bl};

    int gmA = m0 + arow;
    bool okA = gmA < M;
    int gA = okA ? gmA : 0;

    int a_r = (lane & 15), a_c = (lane >> 4) * 8;
    int b_r = (lane & 15), b_c = wn * 64;

    const int KT = K >> 5;
    LOAD_STAGE(0, 0);

    for (int ktile = 0; ktile < KT; ktile++) {
        int cur = ktile & 1;
        if (ktile + 1 < KT) {
            LOAD_STAGE(cur ^ 1, (ktile + 1) << 5);
            cp_wait<1>();
        } else {
            cp_wait<0>();
        }
        __syncthreads();

        #pragma unroll
        for (int ks = 0; ks < 2; ks++) {
            uint32_t afr[2][2][4];
            #pragma unroll
            for (int h = 0; h < 2; h++)
                #pragma unroll
                for (int mt = 0; mt < 2; mt++) {
                    uint32_t addr = (uint32_t)__cvta_generic_to_shared(
                        &AS_(cur, h, wm*32 + mt*16 + a_r, ks*16 + a_c));
                    ldsm_x4(afr[h][mt], addr);
                }
            #pragma unroll
            for (int nt = 0; nt < 8; nt++) {
                uint32_t bfr[2][2];
                #pragma unroll
                for (int h = 0; h < 2; h++) {
                    uint32_t addr = (uint32_t)__cvta_generic_to_shared(
                        &BS_(cur, h, ks*16 + b_r, b_c + nt*8));
                    ldsm_x2t(bfr[h], addr);
                }
                #pragma unroll
                for (int mt = 0; mt < 2; mt++) {
                    mma16816(acc[mt][nt], afr[0][mt], bfr[0]);
                    mma16816(acc[mt][nt], afr[0][mt], bfr[1]);
                    mma16816(acc[mt][nt], afr[1][mt], bfr[0]);
                }
            }
        }
        __syncthreads();
    }

    // epilogue
    int gid = lane >> 2, tig = lane & 3;
    #pragma unroll
    for (int mt = 0; mt < 2; mt++) {
        #pragma unroll
        for (int half = 0; half < 2; half++) {
            int gm = m0 + wm*32 + mt*16 + gid + half*8;
            if (gm >= M) continue;

            int bwq = 0, tq = 0;
            long long ntrow = -1;
            if (mode == 2) { bwq = gm / TT; tq = gm % TT; }
            else if (mode == 3) {
                int bw = gm / TT, t = gm % TT;
                int b = bw / (NWIN*NWIN), wr = bw % (NWIN*NWIN);
                int gh = (wr/NWIN)*WS + t/WS;
                int gw = (wr%NWIN)*WS + t%WS;
                if (gh >= HH || gw >= WW) continue;
                ntrow = (long long)(b*HH + gh)*WW + gw;
            }

            #pragma unroll
            for (int nt = 0; nt < 8; nt++) {
                int col = n0 + wn*64 + nt*8 + tig*2;
                float v0 = acc[mt][nt][half*2 + 0];
                float v1 = acc[mt][nt][half*2 + 1];
                if (bias) { v0 += bias[col]; v1 += bias[col+1]; }
                if (gelu_flag) {
                    v0 = 0.5f * v0 * (1.0f + erff(v0 * 0.70710678118654752440f));
                    v1 = 0.5f * v1 * (1.0f + erff(v1 * 0.70710678118654752440f));
                }
                if (mode == 0) {
                    if (residual) {
                        float2 rr = *reinterpret_cast<const float2*>(
                            residual + (size_t)gm * ldc + col);
                        v0 += rr.x; v1 += rr.y;
                    }
                    *reinterpret_cast<float2*>(Cf + (size_t)gm * ldc + col) =
                        make_float2(v0, v1);
                } else if (mode == 1) {
                    __nv_bfloat16 h0,l0,h1,l1;
                    split2(v0,h0,l0); split2(v1,h1,l1);
                    *reinterpret_cast<__nv_bfloat162*>(Chi + (size_t)gm * ldc + col) =
                        __nv_bfloat162(h0, h1);
                    *reinterpret_cast<__nv_bfloat162*>(Clo + (size_t)gm * ldc + col) =
                        __nv_bfloat162(l0, l1);
                } else if (mode == 2) {
                    int s = col / CC;
                    int r = col - s*CC;
                    int h = r >> 6, d = r & 63;
                    int bb = bwq*NH + h;
                    __nv_bfloat16 h0,l0,h1,l1;
                    split2(v0,h0,l0); split2(v1,h1,l1);
                    if (s == 0) {
                        size_t qi = ((size_t)bb*TT + tq)*HD + d;
                        *reinterpret_cast<__nv_bfloat162*>(qh + qi) = __nv_bfloat162(h0, h1);
                        *reinterpret_cast<__nv_bfloat162*>(ql + qi) = __nv_bfloat162(l0, l1);
                    } else if (s == 1) {
                        size_t kb = (size_t)bb * HD * KTP + tq;
                        kth[kb + (size_t)d*KTP]     = h0;
                        kth[kb + (size_t)(d+1)*KTP] = h1;
                        ktl[kb + (size_t)d*KTP]     = l0;
                        ktl[kb + (size_t)(d+1)*KTP] = l1;
                    } else {
                        size_t vi = ((size_t)bb*TT + tq)*HD + d;
                        *reinterpret_cast<__nv_bfloat162*>(vh + vi) = __nv_bfloat162(h0, h1);
                        *reinterpret_cast<__nv_bfloat162*>(vl + vi) = __nv_bfloat162(l0, l1);
                    }
                } else { // mode 3
                    float2 rr = *reinterpret_cast<const float2*>(
                        residual + ntrow * CC + col);
                    *reinterpret_cast<float2*>(Cf + ntrow * CC + col) =
                        make_float2(v0 + rr.x, v1 + rr.y);
                }
            }
        }
    }
}

// ---------------------------------------------------------------------------
// Batched attention MMA (bf16x3), tile 128x128x32.
//   mode 0 (QK): C = alpha*A@B + relh + relw -> fp32 attn [bz][196][196]
//   mode 1 (PV): C = A@B -> merged-head split bf16 g_ao
// Predicated loads: A rows < M (A col padding is in-bounds & zero),
//                   B rows < K, B cols < ldb.
// ---------------------------------------------------------------------------
#define LOAD_STAGE_ATT(st, k0)                                                 \
  {                                                                            \
    bool okB = ((k0) + brow) < K && (n0 + bcol) < ldb;                         \
    _Pragma("unroll")                                                          \
    for (int h = 0; h < 2; h++) {                                              \
      const __nv_bfloat16* pa = Asrc[h] + (size_t)gA * lda + (k0) + acol;      \
      cp16(&AS_((st),h,arow,acol),   pa,     okA);                             \
      cp16(&AS_((st),h,arow,acol+8), pa + 8, okA);                             \
      const __nv_bfloat16* pb = Bsrc[h] + (size_t)((k0)+brow) * ldb + n0 + bcol; \
      cp16(&BS_((st),h,brow,bcol),   pb,     okB);                             \
      cp16(&BS_((st),h,brow,bcol+8), pb + 8, okB);                             \
    }                                                                          \
    cp_commit();                                                               \
  }

__global__ void __launch_bounds__(256)
attn_mma_kernel(const __nv_bfloat16* __restrict__ Ah_, const __nv_bfloat16* __restrict__ Al_,
                const __nv_bfloat16* __restrict__ Bh_, const __nv_bfloat16* __restrict__ Bl_,
                int M, int N, int K, int lda, int ldb,
                long long sA, long long sB,
                float* __restrict__ qk_out,
                const float* __restrict__ relh, const float* __restrict__ relw,
                float alpha,
                __nv_bfloat16* __restrict__ oh, __nv_bfloat16* __restrict__ ol,
                int mode) {
    extern __shared__ __align__(16) __nv_bfloat16 ds[];

    int bz   = blockIdx.z;
    int tid  = threadIdx.x;
    int wid  = tid >> 5, lane = tid & 31;
    int wm   = wid >> 1, wn = wid & 1;
    int m0   = blockIdx.y * 128;
    int n0   = blockIdx.x * 128;

    float acc[2][8][4];
    #pragma unroll
    for (int mt = 0; mt < 2; mt++)
        #pragma unroll
        for (int nt = 0; nt < 8; nt++)
            #pragma unroll
            for (int c = 0; c < 4; c++) acc[mt][nt][c] = 0.0f;

    int arow = tid >> 1,  acol = (tid & 1) * 16;
    int brow = tid >> 3,  bcol = (tid & 7) * 16;

    const __nv_bfloat16* Asrc[2] = {Ah_ + (size_t)bz*sA, Al_ + (size_t)bz*sA};
    const __nv_bfloat16* Bsrc[2] = {Bh_ + (size_t)bz*sB, Bl_ + (size_t)bz*sB};

    int gmA = m0 + arow;
    bool okA = gmA < M;
    int gA = okA ? gmA : 0;

    int a_r = (lane & 15), a_c = (lane >> 4) * 8;
    int b_r = (lane & 15), b_c = wn * 64;

    const int KT = (K + 31) >> 5;
    LOAD_STAGE_ATT(0, 0);

    for (int ktile = 0; ktile < KT; ktile++) {
        int cur = ktile & 1;
        if (ktile + 1 < KT) {
            LOAD_STAGE_ATT(cur ^ 1, (ktile + 1) << 5);
            cp_wait<1>();
        } else {
            cp_wait<0>();
        }
        __syncthreads();

        #pragma unroll
        for (int ks = 0; ks < 2; ks++) {
            uint32_t afr[2][2][4];
            #pragma unroll
            for (int h = 0; h < 2; h++)
                #pragma unroll
                for (int mt = 0; mt < 2; mt++) {
                    uint32_t addr = (uint32_t)__cvta_generic_to_shared(
                        &AS_(cur, h, wm*32 + mt*16 + a_r, ks*16 + a_c));
                    ldsm_x4(afr[h][mt], addr);
                }
            #pragma unroll
            for (int nt = 0; nt < 8; nt++) {
                uint32_t bfr[2][2];
                #pragma unroll
                for (int h = 0; h < 2; h++) {
                    uint32_t addr = (uint32_t)__cvta_generic_to_shared(
                        &BS_(cur, h, ks*16 + b_r, b_c + nt*8));
                    ldsm_x2t(bfr[h], addr);
                }
                #pragma unroll
                for (int mt = 0; mt < 2; mt++) {
                    mma16816(acc[mt][nt], afr[0][mt], bfr[0]);
                    mma16816(acc[mt][nt], afr[0][mt], bfr[1]);
                    mma16816(acc[mt][nt], afr[1][mt], bfr[0]);
                }
            }
        }
        __syncthreads();
    }

    // epilogue
    int gid = lane >> 2, tig = lane & 3;
    int bwp = bz / NH, hp = bz % NH;
    #pragma unroll
    for (int mt = 0; mt < 2; mt++) {
        #pragma unroll
        for (int half = 0; half < 2; half++) {
            int gm = m0 + wm*32 + mt*16 + gid + half*8;
            if (gm >= M) continue;
            #pragma unroll
            for (int nt = 0; nt < 8; nt++) {
                int col = n0 + wn*64 + nt*8 + tig*2;
                if (col >= N) continue;
                float v0 = acc[mt][nt][half*2 + 0];
                float v1 = acc[mt][nt][half*2 + 1];
                if (mode == 0) {
                    long long rb = (long long)bz * (TT*WS) + (long long)gm * WS;
                    v0 = alpha*v0 + relh[rb + col/WS]     + relw[rb + col%WS];
                    v1 = alpha*v1 + relh[rb + (col+1)/WS] + relw[rb + (col+1)%WS];
                    *reinterpret_cast<float2*>(
                        qk_out + (size_t)bz*TT*TT + (size_t)gm*TT + col) =
                        make_float2(v0, v1);
                } else {
                    __nv_bfloat16 h0,l0,h1,l1;
                    split2(v0,h0,l0); split2(v1,h1,l1);
                    size_t idx = ((size_t)bwp*TT + gm)*CC + hp*HD + col;
                    *reinterpret_cast<__nv_bfloat162*>(oh + idx) = __nv_bfloat162(h0, h1);
                    *reinterpret_cast<__nv_bfloat162*>(ol + idx) = __nv_bfloat162(l0, l1);
                }
            }
        }
    }
}

// ---------------------------------------------------------------------------
// K4: decomposed relative position bias (reads split q)
// ---------------------------------------------------------------------------
__global__ void __launch_bounds__(256)
relbias_kernel(const __nv_bfloat16* __restrict__ qh,
               const __nv_bfloat16* __restrict__ ql,
               const float* __restrict__ rph,
               const float* __restrict__ rpw,
               float* __restrict__ relh, float* __restrict__ relw) {
    int ih = blockIdx.x;        // 0..13
    int b  = blockIdx.y;        // 0..BH-1
    __shared__ float qs[WS][HD+1];
    __shared__ float hs[2*WS-1][HD+1];
    __shared__ float ws[2*WS-1][HD+1];
    int tid = threadIdx.x;
    for (int idx = tid; idx < WS*HD; idx += 256) {
        int iw = idx / HD, d = idx % HD;
        size_t qi = ((size_t)b * TT + ih*WS + iw) * HD + d;
        qs[iw][d] = __bfloat162float(qh[qi]) + __bfloat162float(ql[qi]);
    }
    for (int idx = tid; idx < (2*WS-1)*HD; idx += 256) {
        int r = idx / HD, d = idx % HD;
        hs[r][d] = rph[idx];
        ws[r][d] = rpw[idx];
    }
    __syncthreads();
    for (int tt = tid; tt < 2*TT; tt += 256) {
        int which = tt / TT;
        int l = tt % TT;
        int iw = l / WS, kx = l % WS;
        float sum = 0.0f;
        if (which == 0) {
            int rr = ih - kx + (WS - 1);
            #pragma unroll
            for (int d = 0; d < HD; d++) sum = fmaf(qs[iw][d], hs[rr][d], sum);
            relh[(size_t)b * (TT*WS) + (size_t)(ih*WS + iw) * WS + kx] = sum;
        } else {
            int rr = iw - kx + (WS - 1);
            #pragma unroll
            for (int d = 0; d < HD; d++) sum = fmaf(qs[iw][d], ws[rr][d], sum);
            relw[(size_t)b * (TT*WS) + (size_t)(ih*WS + iw) * WS + kx] = sum;
        }
    }
}

// ---------------------------------------------------------------------------
// K5: softmax over rows of 196; emits split bf16 rows of width KTP (zero pad)
// ---------------------------------------------------------------------------
__global__ void __launch_bounds__(256)
softmax_kernel(const float* __restrict__ attn,
               __nv_bfloat16* __restrict__ ah, __nv_bfloat16* __restrict__ al) {
    int warp = threadIdx.x >> 5, lane = threadIdx.x & 31;
    long long row = (long long)blockIdx.x * 8 + warp;
    if (row >= (long long)BH * TT) return;
    const float* p = attn + row * TT;
    size_t ob = (size_t)row * KTP;
    float v[7];
    float mx = -1e30f;
    #pragma unroll
    for (int i = 0; i < 7; i++) {
        int idx = lane + i*32;
        v[i] = (idx < TT) ? p[idx] : -1e30f;
        mx = fmaxf(mx, v[i]);
    }
    #pragma unroll
    for (int o = 16; o; o >>= 1) mx = fmaxf(mx, __shfl_xor_sync(0xffffffffu, mx, o));
    float s = 0.0f;
    #pragma unroll
    for (int i = 0; i < 7; i++) {
        v[i] = expf(v[i] - mx);
        s += v[i];
    }
    #pragma unroll
    for (int o = 16; o; o >>= 1) s += __shfl_xor_sync(0xffffffffu, s, o);
    float inv = 1.0f / s;
    #pragma unroll
    for (int i = 0; i < 7; i++) {
        int idx = lane + i*32;
        __nv_bfloat16 h, l;
        split2(v[i] * inv, h, l);          // pad lanes: exp->0 -> zero
        ah[ob + idx] = h;
        al[ob + idx] = l;
    }
}

// ---------------------------------------------------------------------------
// Host launcher
// ---------------------------------------------------------------------------
static void launch_mma(const __nv_bfloat16* Ah, const __nv_bfloat16* Al,
                       const __nv_bfloat16* Bh, const __nv_bfloat16* Bl,
                       int M, int N, int K, int lda, int ldb, int ldc,
                       const float* bias, const float* res,
                       float* Cf, __nv_bfloat16* Chi, __nv_bfloat16* Clo,
                       __nv_bfloat16* qh, __nv_bfloat16* ql,
                       __nv_bfloat16* kth, __nv_bfloat16* ktl,
                       __nv_bfloat16* vh, __nv_bfloat16* vl,
                       int mode, int gelu) {
    dim3 grid(N / 128, (M + 127) / 128);
    mma_gemm_kernel<<<grid, 256, MMA_SMEM_BYTES>>>(
        Ah, Al, Bh, Bl, M, N, K, lda, ldb, ldc,
        bias, res, Cf, Chi, Clo, qh, ql, kth, ktl, vh, vl, mode, gelu);
}

extern "C" void kernel_launch(void* const* d_in, const int* in_sizes, int n_in,
                              void* d_out, int out_size) {
    const float* x      = (const float*)d_in[0];
    const float* ln1_g  = (const float*)d_in[1];
    const float* ln1_b  = (const float*)d_in[2];
    const float* w_qkv  = (const float*)d_in[3];
    const float* b_qkv  = (const float*)d_in[4];
    const float* w_proj = (const float*)d_in[5];
    const float* b_proj = (const float*)d_in[6];
    const float* rph    = (const float*)d_in[7];
    const float* rpw    = (const float*)d_in[8];
    const float* ln2_g  = (const float*)d_in[9];
    const float* ln2_b  = (const float*)d_in[10];
    const float* w_fc1  = (const float*)d_in[11];
    const float* b_fc1  = (const float*)d_in[12];
    const float* w_fc2  = (const float*)d_in[13];
    const float* b_fc2  = (const float*)d_in[14];
    float* out = (float*)d_out;

    cudaFuncSetAttribute(mma_gemm_kernel,
                         cudaFuncAttributeMaxDynamicSharedMemorySize, MMA_SMEM_BYTES);
    cudaFuncSetAttribute(attn_mma_kernel,
                         cudaFuncAttributeMaxDynamicSharedMemorySize, MMA_SMEM_BYTES);

    float *p_relh, *p_relw, *p_attn, *p_x2;
    __nv_bfloat16 *p_win_h, *p_win_l, *p_q_h, *p_q_l, *p_kt_h, *p_kt_l,
                  *p_v_h, *p_v_l, *p_at_h, *p_at_l,
                  *p_ao_h, *p_ao_l, *p_ln2_h, *p_ln2_l, *p_mid_h, *p_mid_l,
                  *p_wqkv_h, *p_wqkv_l, *p_wp_h, *p_wp_l,
                  *p_w1_h, *p_w1_l, *p_w2_h, *p_w2_l;
    cudaGetSymbolAddress((void**)&p_relh,  g_relh);
    cudaGetSymbolAddress((void**)&p_relw,  g_relw);
    cudaGetSymbolAddress((void**)&p_attn,  g_attn);
    cudaGetSymbolAddress((void**)&p_x2,    g_x2);
    cudaGetSymbolAddress((void**)&p_win_h, g_win_h);
    cudaGetSymbolAddress((void**)&p_win_l, g_win_l);
    cudaGetSymbolAddress((void**)&p_q_h,   g_q_h);
    cudaGetSymbolAddress((void**)&p_q_l,   g_q_l);
    cudaGetSymbolAddress((void**)&p_kt_h,  g_kt_h);
    cudaGetSymbolAddress((void**)&p_kt_l,  g_kt_l);
    cudaGetSymbolAddress((void**)&p_v_h,   g_v_h);
    cudaGetSymbolAddress((void**)&p_v_l,   g_v_l);
    cudaGetSymbolAddress((void**)&p_at_h,  g_at_h);
    cudaGetSymbolAddress((void**)&p_at_l,  g_at_l);
    cudaGetSymbolAddress((void**)&p_ao_h,  g_ao_h);
    cudaGetSymbolAddress((void**)&p_ao_l,  g_ao_l);
    cudaGetSymbolAddress((void**)&p_ln2_h, g_ln2_h);
    cudaGetSymbolAddress((void**)&p_ln2_l, g_ln2_l);
    cudaGetSymbolAddress((void**)&p_mid_h, g_mid_h);
    cudaGetSymbolAddress((void**)&p_mid_l, g_mid_l);
    cudaGetSymbolAddress((void**)&p_wqkv_h, g_wqkv_h);
    cudaGetSymbolAddress((void**)&p_wqkv_l, g_wqkv_l);
    cudaGetSymbolAddress((void**)&p_wp_h,   g_wp_h);
    cudaGetSymbolAddress((void**)&p_wp_l,   g_wp_l);
    cudaGetSymbolAddress((void**)&p_w1_h,   g_w1_h);
    cudaGetSymbolAddress((void**)&p_w1_l,   g_w1_l);
    cudaGetSymbolAddress((void**)&p_w2_h,   g_w2_h);
    cudaGetSymbolAddress((void**)&p_w2_l,   g_w2_l);

    // 0. split weights to bf16 hi/lo
    {
        int n;
        n = CC*3*CC/4;  split_kernel<<<(n+255)/256, 256>>>(w_qkv,  p_wqkv_h, p_wqkv_l, n);
        n = CC*CC/4;    split_kernel<<<(n+255)/256, 256>>>(w_proj, p_wp_h,   p_wp_l,   n);
        n = CC*4*CC/4;  split_kernel<<<(n+255)/256, 256>>>(w_fc1,  p_w1_h,   p_w1_l,   n);
        n = 4*CC*CC/4;  split_kernel<<<(n+255)/256, 256>>>(w_fc2,  p_w2_h,   p_w2_l,   n);
    }

    // 1. LN1 + window partition (bf16 hi/lo)
    ln1_partition_kernel<<<M1, 256>>>(x, ln1_g, ln1_b, p_win_h, p_win_l);

    // 2. QKV projection with fused split-bf16 repack -> q, k^T (padded), v
    launch_mma(p_win_h, p_win_l, p_wqkv_h, p_wqkv_l,
               M1, 3*CC, CC, CC, 3*CC, 3*CC,
               b_qkv, nullptr, nullptr, nullptr, nullptr,
               p_q_h, p_q_l, p_kt_h, p_kt_l, p_v_h, p_v_l, /*mode=*/2, 0);

    // 3. Rel-pos bias terms
    {
        dim3 grid(WS, BH);
        relbias_kernel<<<grid, 256>>>(p_q_h, p_q_l, rph, rpw, p_relh, p_relw);
    }

    // 4. Scores (tensor cores): attn = 0.125*q@k^T + relh + relw  (fp32 out)
    {
        dim3 grid(2, 2, BH);
        attn_mma_kernel<<<grid, 256, MMA_SMEM_BYTES>>>(
            p_q_h, p_q_l, p_kt_h, p_kt_l,
            TT, TT, HD, HD, KTP,
            (long long)TT*HD, (long long)HD*KTP,
            p_attn, p_relh, p_relw, 0.125f,
            nullptr, nullptr, /*mode=*/0);
    }

    // 5. Softmax -> split bf16 attn weights (padded rows)
    softmax_kernel<<<(BH*TT)/8, 256>>>(p_attn, p_at_h, p_at_l);

    // 6. PV (tensor cores): o = attn @ v, fused head-merge split-bf16 out
    {
        dim3 grid(1, 2, BH);
        attn_mma_kernel<<<grid, 256, MMA_SMEM_BYTES>>>(
            p_at_h, p_at_l, p_v_h, p_v_l,
            TT, HD, TT, KTP, HD,
            (long long)TT*KTP, (long long)TT*HD,
            nullptr, nullptr, nullptr, 1.0f,
            p_ao_h, p_ao_l, /*mode=*/1);
    }

    // 7. Output projection with fused window-reverse + residual -> x2
    launch_mma(p_ao_h, p_ao_l, p_wp_h, p_wp_l,
               M1, CC, CC, CC, CC, CC,
               b_proj, x, p_x2, nullptr, nullptr,
               nullptr, nullptr, nullptr, nullptr, nullptr, nullptr, /*mode=*/3, 0);

    // 8. LN2 -> bf16 hi/lo
    ln2_kernel<<<NT, 256>>>(p_x2, ln2_g, ln2_b, p_ln2_h, p_ln2_l);

    // 9. fc1 + GELU -> bf16 hi/lo intermediate
    launch_mma(p_ln2_h, p_ln2_l, p_w1_h, p_w1_l,
               NT, 4*CC, CC, CC, 4*CC, 4*CC,
               b_fc1, nullptr, nullptr, p_mid_h, p_mid_l,
               nullptr, nullptr, nullptr, nullptr, nullptr, nullptr, /*mode=*/1, 1);

    // 10. fc2 + bias + residual(x2) -> d_out fp32
    launch_mma(p_mid_h, p_mid_l, p_w2_h, p_w2_l,
               NT, CC, 4*CC, 4*CC, CC, CC,
               b_fc2, p_x2, out, nullptr, nullptr,
               nullptr, nullptr, nullptr, nullptr, nullptr, nullptr, /*mode=*/0, 0);
}